// round 1
// baseline (speedup 1.0000x reference)
#include <cuda_runtime.h>
#include <math.h>

// ---------------- dims ----------------
#define B_      128
#define K_      128
#define DIN     256
#define PROJ    64
#define DMODEL  128
#define NLAYER  4
#define PLEN    8
#define STRIDE  4
#define DINNER  256
#define DSTATE  16
#define DTRANK  8
#define NPATCH  32
#define NSEQ    (B_*PROJ)        // 8192

// ---------------- scratch (no cudaMalloc allowed) ----------------
__device__ float g_proj[B_*K_*PROJ];     // 4 MB: clipped projection output
__device__ float g_part[B_*K_];          // per-block abs partial sums
__device__ float g_scale;                // mean(|x|) + 1e-6
__device__ float g_ypred[NSEQ];          // per-(b,c) prediction pre-head

// ---------------- helpers ----------------
__device__ __forceinline__ float siluf(float x) {
    return x / (1.0f + __expf(-x));
}
__device__ __forceinline__ float softplusf(float x) {
    // stable: max(x,0) + log1p(exp(-|x|))
    return fmaxf(x, 0.0f) + log1pf(__expf(-fabsf(x)));
}

// =================================================================
// Kernel 1: x @ proj_w.T + proj_b, clip, per-row(b,k) |.| partials
// grid = B_*K_ blocks, 64 threads (one per output channel)
// =================================================================
__global__ void k_proj(const float* __restrict__ x,
                       const float* __restrict__ pw,
                       const float* __restrict__ pb) {
    int row = blockIdx.x;            // b*K_ + k
    int tid = threadIdx.x;           // 0..63
    __shared__ float xs[DIN];
    __shared__ float red[2];
    for (int i = tid; i < DIN; i += 64) xs[i] = x[row*DIN + i];
    __syncthreads();

    float acc = pb[tid];
    const float* w = pw + tid*DIN;
#pragma unroll 8
    for (int k = 0; k < DIN; k += 4) {
        float4 wv = *(const float4*)(w + k);
        acc = fmaf(wv.x, xs[k+0], acc);
        acc = fmaf(wv.y, xs[k+1], acc);
        acc = fmaf(wv.z, xs[k+2], acc);
        acc = fmaf(wv.w, xs[k+3], acc);
    }
    acc = fminf(5.0f, fmaxf(-5.0f, acc));
    g_proj[row*PROJ + tid] = acc;

    float a = fabsf(acc);
#pragma unroll
    for (int o = 16; o; o >>= 1) a += __shfl_xor_sync(0xffffffffu, a, o);
    if ((tid & 31) == 0) red[tid >> 5] = a;
    __syncthreads();
    if (tid == 0) g_part[row] = red[0] + red[1];
}

// =================================================================
// Kernel 2: deterministic reduction of abs partials -> g_scale
// =================================================================
__global__ void k_reduce() {
    int tid = threadIdx.x;           // 256
    __shared__ float red[8];
    float s = 0.0f;
    for (int i = tid; i < B_*K_; i += 256) s += g_part[i];
#pragma unroll
    for (int o = 16; o; o >>= 1) s += __shfl_xor_sync(0xffffffffu, s, o);
    if ((tid & 31) == 0) red[tid >> 5] = s;
    __syncthreads();
    if (tid == 0) {
        float t = 0.0f;
#pragma unroll
        for (int i = 0; i < 8; i++) t += red[i];
        g_scale = t * (1.0f/(float)(B_*K_*PROJ)) + 1e-6f;
    }
}

// =================================================================
// Mega-kernel: one block per sequence (b,c).
// instance-norm -> patch embed -> 4 Mamba layers -> rmsnorm -> headb dot
// =================================================================
// shared memory layout (floats)
#define OFF_H    0
#define OFF_HN   4096
#define OFF_XR   8192       // 32 x 512 : [xc | res], later [ys | partials]
#define OFF_DBL  24576      // 32 x 40
#define OFF_XN   25856      // 132 (+pad)
#define OFF_RED  25992      // 8 warp partials
#define OFF_MISC 26024      // mu, sd
#define SMEM_FLOATS 26032   // 104128 bytes -> 2 blocks / SM

__device__ __forceinline__ float block_reduce256(float v, float* red) {
#pragma unroll
    for (int o = 16; o; o >>= 1) v += __shfl_xor_sync(0xffffffffu, v, o);
    int wid = threadIdx.x >> 5;
    if ((threadIdx.x & 31) == 0) red[wid] = v;
    __syncthreads();
    if (threadIdx.x == 0) {
        float t = 0.0f;
#pragma unroll
        for (int i = 0; i < 8; i++) t += red[i];
        red[0] = t;
    }
    __syncthreads();
    float r = red[0];
    __syncthreads();   // protect red[] for back-to-back use
    return r;
}

__global__ void __launch_bounds__(256, 2) k_mamba(
    const float* __restrict__ emb_w,   const float* __restrict__ emb_b,
    const float* __restrict__ norm_w,  const float* __restrict__ inproj_w,
    const float* __restrict__ conv_w,  const float* __restrict__ conv_b,
    const float* __restrict__ xproj_w, const float* __restrict__ dtproj_w,
    const float* __restrict__ dtproj_b,const float* __restrict__ A_log,
    const float* __restrict__ D_p,     const float* __restrict__ outproj_w,
    const float* __restrict__ normf_w, const float* __restrict__ headb_w,
    const float* __restrict__ headb_b)
{
    extern __shared__ float sm[];
    float* sh    = sm + OFF_H;     // residual stream 32x128
    float* shn   = sm + OFF_HN;    // normed copy     32x128
    float* sxr   = sm + OFF_XR;    // 32x512
    float* sdbl  = sm + OFF_DBL;   // 32x40
    float* sxn   = sm + OFF_XN;    // padded channel 132
    float* sred  = sm + OFF_RED;
    float* smisc = sm + OFF_MISC;

    const int tid = threadIdx.x;
    const int seq = blockIdx.x;
    const int b   = seq >> 6;
    const int c   = seq & 63;

    // -------- Phase A: scale + instance norm over K --------
    const float inv_s = 1.0f / g_scale;
    float val = 0.0f;
    if (tid < K_) val = g_proj[(b*K_ + tid)*PROJ + c] * inv_s;
    float su = block_reduce256(tid < K_ ? val : 0.0f, sred);
    float sq = block_reduce256(tid < K_ ? val*val : 0.0f, sred);
    float mu  = su * (1.0f/(float)K_);
    float var = sq * (1.0f/(float)K_) - mu*mu;
    float sd  = sqrtf(var + 1e-5f);
    float rsd = 1.0f / sd;
    if (tid < K_) sxn[tid] = (val - mu) * rsd;
    if (tid == 0) { smisc[0] = mu; smisc[1] = sd; }
    __syncthreads();
    if (tid < STRIDE) sxn[K_ + tid] = sxn[K_ - 1];  // replication pad
    __syncthreads();

    // -------- Phase B: patch embedding -> h --------
    {
        int m  = tid & 127;
        int n0 = tid >> 7;
        float4 e0 = *(const float4*)(emb_w + m*PLEN);
        float4 e1 = *(const float4*)(emb_w + m*PLEN + 4);
        float  eb = emb_b[m];
        for (int n = n0; n < NPATCH; n += 2) {
            const float* xp = sxn + n*STRIDE;
            float v = eb;
            v = fmaf(e0.x, xp[0], v); v = fmaf(e0.y, xp[1], v);
            v = fmaf(e0.z, xp[2], v); v = fmaf(e0.w, xp[3], v);
            v = fmaf(e1.x, xp[4], v); v = fmaf(e1.y, xp[5], v);
            v = fmaf(e1.z, xp[6], v); v = fmaf(e1.w, xp[7], v);
            sh[n*DMODEL + m] = v;
        }
    }
    __syncthreads();

    // -------- Phase C: 4 Mamba layers --------
    for (int L = 0; L < NLAYER; L++) {
        // 1. rmsnorm(h) * norm_w[L] -> hn   (warp per 4 rows)
        {
            int wid = tid >> 5, lane = tid & 31;
            const float* wv = norm_w + L*DMODEL;
            float4 wv4 = *(const float4*)(wv + lane*4);
#pragma unroll
            for (int r = wid*4; r < wid*4 + 4; r++) {
                float4 hv = *(const float4*)(sh + r*DMODEL + lane*4);
                float ss = hv.x*hv.x + hv.y*hv.y + hv.z*hv.z + hv.w*hv.w;
#pragma unroll
                for (int o = 16; o; o >>= 1) ss += __shfl_xor_sync(0xffffffffu, ss, o);
                float rms = rsqrtf(ss*(1.0f/(float)DMODEL) + 1e-5f);
                float4 ov;
                ov.x = hv.x*rms*wv4.x; ov.y = hv.y*rms*wv4.y;
                ov.z = hv.z*rms*wv4.z; ov.w = hv.w*rms*wv4.w;
                *(float4*)(shn + r*DMODEL + lane*4) = ov;
            }
        }
        __syncthreads();

        // 2. inproj: xr[t][j] = hn[t][:] . W[j][:]   (j = tid, tid+256)
        {
            const float* Wb = inproj_w + (size_t)L*2*DINNER*DMODEL;
#pragma unroll
            for (int jj = 0; jj < 2; jj++) {
                int j = tid + jj*256;
                const float* W = Wb + j*DMODEL;
                float acc[NPATCH];
#pragma unroll
                for (int t = 0; t < NPATCH; t++) acc[t] = 0.0f;
                for (int k = 0; k < DMODEL; k += 4) {
                    float4 w = *(const float4*)(W + k);
#pragma unroll
                    for (int t = 0; t < NPATCH; t++) {
                        float4 hv = *(const float4*)(shn + t*DMODEL + k);  // LDS.128 broadcast
                        acc[t] = fmaf(w.x, hv.x, fmaf(w.y, hv.y,
                                 fmaf(w.z, hv.z, fmaf(w.w, hv.w, acc[t]))));
                    }
                }
#pragma unroll
                for (int t = 0; t < NPATCH; t++) sxr[t*512 + j] = acc[t];
            }
        }
        __syncthreads();

        // 3. causal depthwise conv(4) + bias + silu, in place on xc
        {
            int d = tid;
            float4 w  = *(const float4*)(conv_w + (size_t)(L*DINNER + d)*4);
            float  cb = conv_b[L*DINNER + d];
            float x0 = 0.0f, x1 = 0.0f, x2 = 0.0f;
#pragma unroll
            for (int t = 0; t < NPATCH; t++) {
                float xt = sxr[t*512 + d];
                float o = fmaf(w.x, x0, fmaf(w.y, x1, fmaf(w.z, x2, fmaf(w.w, xt, cb))));
                sxr[t*512 + d] = siluf(o);
                x0 = x1; x1 = x2; x2 = xt;
            }
        }
        __syncthreads();

        // 4. xproj: dbl[t][q] = xc[t][:] . W[q][:]   (1280 outputs, 5 per thread)
        {
            const float* Wb = xproj_w + (size_t)L*(DTRANK+2*DSTATE)*DINNER;
#pragma unroll
            for (int r = 0; r < 5; r++) {
                int o = r*256 + tid;
                int t = o / 40, q = o % 40;
                const float* W = Wb + q*DINNER;
                float acc = 0.0f;
                for (int dd = 0; dd < DINNER; dd += 4) {
                    float4 w  = *(const float4*)(W + dd);
                    float4 xv = *(const float4*)(sxr + t*512 + dd);
                    acc = fmaf(w.x, xv.x, fmaf(w.y, xv.y,
                          fmaf(w.z, xv.z, fmaf(w.w, xv.w, acc))));
                }
                sdbl[t*40 + q] = acc;
            }
        }
        __syncthreads();

        // 5. selective scan (thread d owns channel d; 16 states in regs)
        {
            int d = tid;
            float4 dw0 = *(const float4*)(dtproj_w + (size_t)(L*DINNER + d)*DTRANK);
            float4 dw1 = *(const float4*)(dtproj_w + (size_t)(L*DINNER + d)*DTRANK + 4);
            float  dtb = dtproj_b[L*DINNER + d];
            float  Dp  = D_p[L*DINNER + d];
            float  A[DSTATE];
            const float* Al = A_log + (size_t)(L*DINNER + d)*DSTATE;
#pragma unroll
            for (int n = 0; n < DSTATE; n++) A[n] = -expf(Al[n]);
            float st[DSTATE];
#pragma unroll
            for (int n = 0; n < DSTATE; n++) st[n] = 0.0f;

            for (int t = 0; t < NPATCH; t++) {
                const float* db = sdbl + t*40;
                float dtv = dtb;
                dtv = fmaf(dw0.x, db[0], dtv); dtv = fmaf(dw0.y, db[1], dtv);
                dtv = fmaf(dw0.z, db[2], dtv); dtv = fmaf(dw0.w, db[3], dtv);
                dtv = fmaf(dw1.x, db[4], dtv); dtv = fmaf(dw1.y, db[5], dtv);
                dtv = fmaf(dw1.z, db[6], dtv); dtv = fmaf(dw1.w, db[7], dtv);
                dtv = softplusf(dtv);

                float u = sxr[t*512 + d];
                float y = 0.0f;
#pragma unroll
                for (int n = 0; n < DSTATE; n++) {
                    float dA = __expf(dtv * A[n]);
                    st[n] = fmaf(st[n], dA, dtv * db[8+n] * u);
                    y = fmaf(st[n], db[24+n], y);
                }
                y = fmaf(u, Dp, y);
                float rv = sxr[t*512 + DINNER + d];
                sxr[t*512 + d] = y * siluf(rv);   // ys overwrites xc slot
            }
        }
        __syncthreads();

        // 6. outproj + residual add (two d-halves; partials into dead res region)
        {
            int m  = tid & 127, dh = tid >> 7;
            const float* W = outproj_w + (size_t)(L*DMODEL + m)*DINNER + dh*128;
            float acc[NPATCH];
#pragma unroll
            for (int t = 0; t < NPATCH; t++) acc[t] = 0.0f;
            for (int dd = 0; dd < 128; dd += 4) {
                float4 w = *(const float4*)(W + dd);
                int dpos = dh*128 + dd;
#pragma unroll
                for (int t = 0; t < NPATCH; t++) {
                    float4 yv = *(const float4*)(sxr + t*512 + dpos);  // broadcast
                    acc[t] = fmaf(w.x, yv.x, fmaf(w.y, yv.y,
                             fmaf(w.z, yv.z, fmaf(w.w, yv.w, acc[t]))));
                }
            }
#pragma unroll
            for (int t = 0; t < NPATCH; t++)
                sxr[t*512 + DINNER + dh*128 + m] = acc[t];
        }
        __syncthreads();
        for (int o = tid; o < NPATCH*DMODEL; o += 256) {
            int t = o >> 7, m = o & 127;
            sh[o] += sxr[t*512 + DINNER + m] + sxr[t*512 + DINNER + 128 + m];
        }
        __syncthreads();
    }

    // -------- Phase D: final rmsnorm + headb dot + denorm --------
    {
        int wid = tid >> 5, lane = tid & 31;
        float4 wv4 = *(const float4*)(normf_w + lane*4);
#pragma unroll
        for (int r = wid*4; r < wid*4 + 4; r++) {
            float4 hv = *(const float4*)(sh + r*DMODEL + lane*4);
            float ss = hv.x*hv.x + hv.y*hv.y + hv.z*hv.z + hv.w*hv.w;
#pragma unroll
            for (int o = 16; o; o >>= 1) ss += __shfl_xor_sync(0xffffffffu, ss, o);
            float rms = rsqrtf(ss*(1.0f/(float)DMODEL) + 1e-5f);
            float4 ov;
            ov.x = hv.x*rms*wv4.x; ov.y = hv.y*rms*wv4.y;
            ov.z = hv.z*rms*wv4.z; ov.w = hv.w*rms*wv4.w;
            *(float4*)(shn + r*DMODEL + lane*4) = ov;
        }
    }
    __syncthreads();

    float loc = 0.0f;
    for (int o = tid; o < NPATCH*DMODEL; o += 256) loc += shn[o]*headb_w[o];
    float tot = block_reduce256(loc, sred);
    if (tid == 0) {
        float yv = tot + headb_b[0];
        g_ypred[seq] = yv * smisc[1] + smisc[0];   // denorm with scaled stats
    }
}

// =================================================================
// Kernel 4: final head  (128,64) @ (64,2)
// =================================================================
__global__ void k_head(const float* __restrict__ head_w,
                       const float* __restrict__ head_b,
                       float* __restrict__ out) {
    int tid = threadIdx.x;          // 256 = 128 b x 2 o
    int b = tid >> 1, o = tid & 1;
    float acc = head_b[o];
    const float* w = head_w + o*PROJ;
#pragma unroll 8
    for (int c = 0; c < PROJ; c++) acc = fmaf(g_ypred[b*PROJ + c], w[c], acc);
    out[b*2 + o] = acc;
}

// =================================================================
// launch
// =================================================================
extern "C" void kernel_launch(void* const* d_in, const int* in_sizes, int n_in,
                              void* d_out, int out_size) {
    const float* x         = (const float*)d_in[0];
    const float* proj_w    = (const float*)d_in[1];
    const float* proj_b    = (const float*)d_in[2];
    const float* emb_w     = (const float*)d_in[3];
    const float* emb_b     = (const float*)d_in[4];
    const float* norm_w    = (const float*)d_in[5];
    const float* inproj_w  = (const float*)d_in[6];
    const float* conv_w    = (const float*)d_in[7];
    const float* conv_b    = (const float*)d_in[8];
    const float* xproj_w   = (const float*)d_in[9];
    const float* dtproj_w  = (const float*)d_in[10];
    const float* dtproj_b  = (const float*)d_in[11];
    const float* A_log     = (const float*)d_in[12];
    const float* D_p       = (const float*)d_in[13];
    const float* outproj_w = (const float*)d_in[14];
    const float* normf_w   = (const float*)d_in[15];
    const float* headb_w   = (const float*)d_in[16];
    const float* headb_b   = (const float*)d_in[17];
    const float* head_w    = (const float*)d_in[18];
    const float* head_b    = (const float*)d_in[19];

    cudaFuncSetAttribute(k_mamba, cudaFuncAttributeMaxDynamicSharedMemorySize,
                         SMEM_FLOATS * sizeof(float));

    k_proj<<<B_*K_, 64>>>(x, proj_w, proj_b);
    k_reduce<<<1, 256>>>();
    k_mamba<<<NSEQ, 256, SMEM_FLOATS * sizeof(float)>>>(
        emb_w, emb_b, norm_w, inproj_w, conv_w, conv_b, xproj_w,
        dtproj_w, dtproj_b, A_log, D_p, outproj_w, normf_w, headb_w, headb_b);
    k_head<<<1, 256>>>(head_w, head_b, (float*)d_out);
}

// round 2
// speedup vs baseline: 1.0003x; 1.0003x over previous
#include <cuda_runtime.h>
#include <math.h>

// ---------------- dims ----------------
#define B_      128
#define K_      128
#define DIN     256
#define PROJ    64
#define DMODEL  128
#define NLAYER  4
#define PLEN    8
#define STRIDE  4
#define DINNER  256
#define DSTATE  16
#define DTRANK  8
#define NPATCH  32
#define NSEQ    (B_*PROJ)        // 8192

// ---------------- scratch (no cudaMalloc allowed) ----------------
__device__ float g_proj[B_*K_*PROJ];     // 4 MB: clipped projection output
__device__ float g_part[B_*K_];          // per-block abs partial sums
__device__ float g_scale;                // mean(|x|) + 1e-6
__device__ float g_ypred[NSEQ];          // per-(b,c) prediction pre-head

// ---------------- helpers ----------------
__device__ __forceinline__ float siluf(float x) {
    return x / (1.0f + __expf(-x));
}
__device__ __forceinline__ float softplusf(float x) {
    // stable: max(x,0) + log1p(exp(-|x|))
    return fmaxf(x, 0.0f) + log1pf(__expf(-fabsf(x)));
}

// =================================================================
// Kernel 1: x @ proj_w.T + proj_b, clip, per-row(b,k) |.| partials
// grid = B_*K_ blocks, 64 threads (one per output channel)
// =================================================================
__global__ void k_proj(const float* __restrict__ x,
                       const float* __restrict__ pw,
                       const float* __restrict__ pb) {
    int row = blockIdx.x;            // b*K_ + k
    int tid = threadIdx.x;           // 0..63
    __shared__ float xs[DIN];
    __shared__ float red[2];
    for (int i = tid; i < DIN; i += 64) xs[i] = x[row*DIN + i];
    __syncthreads();

    float acc = pb[tid];
    const float* w = pw + tid*DIN;
#pragma unroll 8
    for (int k = 0; k < DIN; k += 4) {
        float4 wv = *(const float4*)(w + k);
        acc = fmaf(wv.x, xs[k+0], acc);
        acc = fmaf(wv.y, xs[k+1], acc);
        acc = fmaf(wv.z, xs[k+2], acc);
        acc = fmaf(wv.w, xs[k+3], acc);
    }
    acc = fminf(5.0f, fmaxf(-5.0f, acc));
    g_proj[row*PROJ + tid] = acc;

    float a = fabsf(acc);
#pragma unroll
    for (int o = 16; o; o >>= 1) a += __shfl_xor_sync(0xffffffffu, a, o);
    if ((tid & 31) == 0) red[tid >> 5] = a;
    __syncthreads();
    if (tid == 0) g_part[row] = red[0] + red[1];
}

// =================================================================
// Kernel 2: deterministic reduction of abs partials -> g_scale
// =================================================================
__global__ void k_reduce() {
    int tid = threadIdx.x;           // 256
    __shared__ float red[8];
    float s = 0.0f;
    for (int i = tid; i < B_*K_; i += 256) s += g_part[i];
#pragma unroll
    for (int o = 16; o; o >>= 1) s += __shfl_xor_sync(0xffffffffu, s, o);
    if ((tid & 31) == 0) red[tid >> 5] = s;
    __syncthreads();
    if (tid == 0) {
        float t = 0.0f;
#pragma unroll
        for (int i = 0; i < 8; i++) t += red[i];
        g_scale = t * (1.0f/(float)(B_*K_*PROJ)) + 1e-6f;
    }
}

// =================================================================
// Mega-kernel: one block per sequence (b,c).
// instance-norm -> patch embed -> 4 Mamba layers -> rmsnorm -> headb dot
// =================================================================
// shared memory layout (floats)
#define OFF_H    0
#define OFF_HN   4096
#define OFF_XR   8192       // 32 x 512 : [xc | res], later [ys | partials]
#define OFF_DBL  24576      // 32 x 40
#define OFF_XN   25856      // 132 (+pad)
#define OFF_RED  25992      // 8 warp partials
#define OFF_MISC 26024      // mu, sd
#define SMEM_FLOATS 26032   // 104128 bytes -> 2 blocks / SM

__device__ __forceinline__ float block_reduce256(float v, float* red) {
#pragma unroll
    for (int o = 16; o; o >>= 1) v += __shfl_xor_sync(0xffffffffu, v, o);
    int wid = threadIdx.x >> 5;
    if ((threadIdx.x & 31) == 0) red[wid] = v;
    __syncthreads();
    if (threadIdx.x == 0) {
        float t = 0.0f;
#pragma unroll
        for (int i = 0; i < 8; i++) t += red[i];
        red[0] = t;
    }
    __syncthreads();
    float r = red[0];
    __syncthreads();   // protect red[] for back-to-back use
    return r;
}

__global__ void __launch_bounds__(256, 2) k_mamba(
    const float* __restrict__ emb_w,   const float* __restrict__ emb_b,
    const float* __restrict__ norm_w,  const float* __restrict__ inproj_w,
    const float* __restrict__ conv_w,  const float* __restrict__ conv_b,
    const float* __restrict__ xproj_w, const float* __restrict__ dtproj_w,
    const float* __restrict__ dtproj_b,const float* __restrict__ A_log,
    const float* __restrict__ D_p,     const float* __restrict__ outproj_w,
    const float* __restrict__ normf_w, const float* __restrict__ headb_w,
    const float* __restrict__ headb_b)
{
    extern __shared__ float sm[];
    float* sh    = sm + OFF_H;     // residual stream 32x128
    float* shn   = sm + OFF_HN;    // normed copy     32x128
    float* sxr   = sm + OFF_XR;    // 32x512
    float* sdbl  = sm + OFF_DBL;   // 32x40
    float* sxn   = sm + OFF_XN;    // padded channel 132
    float* sred  = sm + OFF_RED;
    float* smisc = sm + OFF_MISC;

    const int tid = threadIdx.x;
    const int seq = blockIdx.x;
    const int b   = seq >> 6;
    const int c   = seq & 63;

    // -------- Phase A: scale + instance norm over K --------
    const float inv_s = 1.0f / g_scale;
    float val = 0.0f;
    if (tid < K_) val = g_proj[(b*K_ + tid)*PROJ + c] * inv_s;
    float su = block_reduce256(tid < K_ ? val : 0.0f, sred);
    float sq = block_reduce256(tid < K_ ? val*val : 0.0f, sred);
    float mu  = su * (1.0f/(float)K_);
    float var = sq * (1.0f/(float)K_) - mu*mu;
    float sd  = sqrtf(var + 1e-5f);
    float rsd = 1.0f / sd;
    if (tid < K_) sxn[tid] = (val - mu) * rsd;
    if (tid == 0) { smisc[0] = mu; smisc[1] = sd; }
    __syncthreads();
    if (tid < STRIDE) sxn[K_ + tid] = sxn[K_ - 1];  // replication pad
    __syncthreads();

    // -------- Phase B: patch embedding -> h --------
    {
        int m  = tid & 127;
        int n0 = tid >> 7;
        float4 e0 = *(const float4*)(emb_w + m*PLEN);
        float4 e1 = *(const float4*)(emb_w + m*PLEN + 4);
        float  eb = emb_b[m];
        for (int n = n0; n < NPATCH; n += 2) {
            const float* xp = sxn + n*STRIDE;
            float v = eb;
            v = fmaf(e0.x, xp[0], v); v = fmaf(e0.y, xp[1], v);
            v = fmaf(e0.z, xp[2], v); v = fmaf(e0.w, xp[3], v);
            v = fmaf(e1.x, xp[4], v); v = fmaf(e1.y, xp[5], v);
            v = fmaf(e1.z, xp[6], v); v = fmaf(e1.w, xp[7], v);
            sh[n*DMODEL + m] = v;
        }
    }
    __syncthreads();

    // -------- Phase C: 4 Mamba layers --------
    for (int L = 0; L < NLAYER; L++) {
        // 1. rmsnorm(h) * norm_w[L] -> hn   (warp per 4 rows)
        {
            int wid = tid >> 5, lane = tid & 31;
            const float* wv = norm_w + L*DMODEL;
            float4 wv4 = *(const float4*)(wv + lane*4);
#pragma unroll
            for (int r = wid*4; r < wid*4 + 4; r++) {
                float4 hv = *(const float4*)(sh + r*DMODEL + lane*4);
                float ss = hv.x*hv.x + hv.y*hv.y + hv.z*hv.z + hv.w*hv.w;
#pragma unroll
                for (int o = 16; o; o >>= 1) ss += __shfl_xor_sync(0xffffffffu, ss, o);
                float rms = rsqrtf(ss*(1.0f/(float)DMODEL) + 1e-5f);
                float4 ov;
                ov.x = hv.x*rms*wv4.x; ov.y = hv.y*rms*wv4.y;
                ov.z = hv.z*rms*wv4.z; ov.w = hv.w*rms*wv4.w;
                *(float4*)(shn + r*DMODEL + lane*4) = ov;
            }
        }
        __syncthreads();

        // 2. inproj: xr[t][j] = hn[t][:] . W[j][:]   (j = tid, tid+256)
        {
            const float* Wb = inproj_w + (size_t)L*2*DINNER*DMODEL;
#pragma unroll
            for (int jj = 0; jj < 2; jj++) {
                int j = tid + jj*256;
                const float* W = Wb + j*DMODEL;
                float acc[NPATCH];
#pragma unroll
                for (int t = 0; t < NPATCH; t++) acc[t] = 0.0f;
                for (int k = 0; k < DMODEL; k += 4) {
                    float4 w = *(const float4*)(W + k);
#pragma unroll
                    for (int t = 0; t < NPATCH; t++) {
                        float4 hv = *(const float4*)(shn + t*DMODEL + k);  // LDS.128 broadcast
                        acc[t] = fmaf(w.x, hv.x, fmaf(w.y, hv.y,
                                 fmaf(w.z, hv.z, fmaf(w.w, hv.w, acc[t]))));
                    }
                }
#pragma unroll
                for (int t = 0; t < NPATCH; t++) sxr[t*512 + j] = acc[t];
            }
        }
        __syncthreads();

        // 3. causal depthwise conv(4) + bias + silu, in place on xc
        {
            int d = tid;
            float4 w  = *(const float4*)(conv_w + (size_t)(L*DINNER + d)*4);
            float  cb = conv_b[L*DINNER + d];
            float x0 = 0.0f, x1 = 0.0f, x2 = 0.0f;
#pragma unroll
            for (int t = 0; t < NPATCH; t++) {
                float xt = sxr[t*512 + d];
                float o = fmaf(w.x, x0, fmaf(w.y, x1, fmaf(w.z, x2, fmaf(w.w, xt, cb))));
                sxr[t*512 + d] = siluf(o);
                x0 = x1; x1 = x2; x2 = xt;
            }
        }
        __syncthreads();

        // 4. xproj: dbl[t][q] = xc[t][:] . W[q][:]   (1280 outputs, 5 per thread)
        {
            const float* Wb = xproj_w + (size_t)L*(DTRANK+2*DSTATE)*DINNER;
#pragma unroll
            for (int r = 0; r < 5; r++) {
                int o = r*256 + tid;
                int t = o / 40, q = o % 40;
                const float* W = Wb + q*DINNER;
                float acc = 0.0f;
                for (int dd = 0; dd < DINNER; dd += 4) {
                    float4 w  = *(const float4*)(W + dd);
                    float4 xv = *(const float4*)(sxr + t*512 + dd);
                    acc = fmaf(w.x, xv.x, fmaf(w.y, xv.y,
                          fmaf(w.z, xv.z, fmaf(w.w, xv.w, acc))));
                }
                sdbl[t*40 + q] = acc;
            }
        }
        __syncthreads();

        // 5. selective scan (thread d owns channel d; 16 states in regs)
        {
            int d = tid;
            float4 dw0 = *(const float4*)(dtproj_w + (size_t)(L*DINNER + d)*DTRANK);
            float4 dw1 = *(const float4*)(dtproj_w + (size_t)(L*DINNER + d)*DTRANK + 4);
            float  dtb = dtproj_b[L*DINNER + d];
            float  Dp  = D_p[L*DINNER + d];
            float  A[DSTATE];
            const float* Al = A_log + (size_t)(L*DINNER + d)*DSTATE;
#pragma unroll
            for (int n = 0; n < DSTATE; n++) A[n] = -expf(Al[n]);
            float st[DSTATE];
#pragma unroll
            for (int n = 0; n < DSTATE; n++) st[n] = 0.0f;

            for (int t = 0; t < NPATCH; t++) {
                const float* db = sdbl + t*40;
                float dtv = dtb;
                dtv = fmaf(dw0.x, db[0], dtv); dtv = fmaf(dw0.y, db[1], dtv);
                dtv = fmaf(dw0.z, db[2], dtv); dtv = fmaf(dw0.w, db[3], dtv);
                dtv = fmaf(dw1.x, db[4], dtv); dtv = fmaf(dw1.y, db[5], dtv);
                dtv = fmaf(dw1.z, db[6], dtv); dtv = fmaf(dw1.w, db[7], dtv);
                dtv = softplusf(dtv);

                float u = sxr[t*512 + d];
                float y = 0.0f;
#pragma unroll
                for (int n = 0; n < DSTATE; n++) {
                    float dA = __expf(dtv * A[n]);
                    st[n] = fmaf(st[n], dA, dtv * db[8+n] * u);
                    y = fmaf(st[n], db[24+n], y);
                }
                y = fmaf(u, Dp, y);
                float rv = sxr[t*512 + DINNER + d];
                sxr[t*512 + d] = y * siluf(rv);   // ys overwrites xc slot
            }
        }
        __syncthreads();

        // 6. outproj + residual add (two d-halves; partials into dead res region)
        {
            int m  = tid & 127, dh = tid >> 7;
            const float* W = outproj_w + (size_t)(L*DMODEL + m)*DINNER + dh*128;
            float acc[NPATCH];
#pragma unroll
            for (int t = 0; t < NPATCH; t++) acc[t] = 0.0f;
            for (int dd = 0; dd < 128; dd += 4) {
                float4 w = *(const float4*)(W + dd);
                int dpos = dh*128 + dd;
#pragma unroll
                for (int t = 0; t < NPATCH; t++) {
                    float4 yv = *(const float4*)(sxr + t*512 + dpos);  // broadcast
                    acc[t] = fmaf(w.x, yv.x, fmaf(w.y, yv.y,
                             fmaf(w.z, yv.z, fmaf(w.w, yv.w, acc[t]))));
                }
            }
#pragma unroll
            for (int t = 0; t < NPATCH; t++)
                sxr[t*512 + DINNER + dh*128 + m] = acc[t];
        }
        __syncthreads();
        for (int o = tid; o < NPATCH*DMODEL; o += 256) {
            int t = o >> 7, m = o & 127;
            sh[o] += sxr[t*512 + DINNER + m] + sxr[t*512 + DINNER + 128 + m];
        }
        __syncthreads();
    }

    // -------- Phase D: final rmsnorm + headb dot + denorm --------
    {
        int wid = tid >> 5, lane = tid & 31;
        float4 wv4 = *(const float4*)(normf_w + lane*4);
#pragma unroll
        for (int r = wid*4; r < wid*4 + 4; r++) {
            float4 hv = *(const float4*)(sh + r*DMODEL + lane*4);
            float ss = hv.x*hv.x + hv.y*hv.y + hv.z*hv.z + hv.w*hv.w;
#pragma unroll
            for (int o = 16; o; o >>= 1) ss += __shfl_xor_sync(0xffffffffu, ss, o);
            float rms = rsqrtf(ss*(1.0f/(float)DMODEL) + 1e-5f);
            float4 ov;
            ov.x = hv.x*rms*wv4.x; ov.y = hv.y*rms*wv4.y;
            ov.z = hv.z*rms*wv4.z; ov.w = hv.w*rms*wv4.w;
            *(float4*)(shn + r*DMODEL + lane*4) = ov;
        }
    }
    __syncthreads();

    float loc = 0.0f;
    for (int o = tid; o < NPATCH*DMODEL; o += 256) loc += shn[o]*headb_w[o];
    float tot = block_reduce256(loc, sred);
    if (tid == 0) {
        float yv = tot + headb_b[0];
        g_ypred[seq] = yv * smisc[1] + smisc[0];   // denorm with scaled stats
    }
}

// =================================================================
// Kernel 4: final head  (128,64) @ (64,2)
// =================================================================
__global__ void k_head(const float* __restrict__ head_w,
                       const float* __restrict__ head_b,
                       float* __restrict__ out) {
    int tid = threadIdx.x;          // 256 = 128 b x 2 o
    int b = tid >> 1, o = tid & 1;
    float acc = head_b[o];
    const float* w = head_w + o*PROJ;
#pragma unroll 8
    for (int c = 0; c < PROJ; c++) acc = fmaf(g_ypred[b*PROJ + c], w[c], acc);
    out[b*2 + o] = acc;
}

// =================================================================
// launch
// =================================================================
extern "C" void kernel_launch(void* const* d_in, const int* in_sizes, int n_in,
                              void* d_out, int out_size) {
    const float* x         = (const float*)d_in[0];
    const float* proj_w    = (const float*)d_in[1];
    const float* proj_b    = (const float*)d_in[2];
    const float* emb_w     = (const float*)d_in[3];
    const float* emb_b     = (const float*)d_in[4];
    const float* norm_w    = (const float*)d_in[5];
    const float* inproj_w  = (const float*)d_in[6];
    const float* conv_w    = (const float*)d_in[7];
    const float* conv_b    = (const float*)d_in[8];
    const float* xproj_w   = (const float*)d_in[9];
    const float* dtproj_w  = (const float*)d_in[10];
    const float* dtproj_b  = (const float*)d_in[11];
    const float* A_log     = (const float*)d_in[12];
    const float* D_p       = (const float*)d_in[13];
    const float* outproj_w = (const float*)d_in[14];
    const float* normf_w   = (const float*)d_in[15];
    const float* headb_w   = (const float*)d_in[16];
    const float* headb_b   = (const float*)d_in[17];
    const float* head_w    = (const float*)d_in[18];
    const float* head_b    = (const float*)d_in[19];

    cudaFuncSetAttribute(k_mamba, cudaFuncAttributeMaxDynamicSharedMemorySize,
                         SMEM_FLOATS * sizeof(float));

    k_proj<<<B_*K_, 64>>>(x, proj_w, proj_b);
    k_reduce<<<1, 256>>>();
    k_mamba<<<NSEQ, 256, SMEM_FLOATS * sizeof(float)>>>(
        emb_w, emb_b, norm_w, inproj_w, conv_w, conv_b, xproj_w,
        dtproj_w, dtproj_b, A_log, D_p, outproj_w, normf_w, headb_w, headb_b);
    k_head<<<1, 256>>>(head_w, head_b, (float*)d_out);
}

// round 4
// speedup vs baseline: 2.1277x; 2.1272x over previous
#include <cuda_runtime.h>
#include <math.h>

// ---------------- dims ----------------
#define B_      128
#define K_      128
#define DIN     256
#define PROJ    64
#define DMODEL  128
#define NLAYER  4
#define PLEN    8
#define STRIDE  4
#define DINNER  256
#define DSTATE  16
#define DTRANK  8
#define NPATCH  32
#define NSEQ    (B_*PROJ)        // 8192

typedef unsigned long long ull;
struct __align__(16) ull2 { ull x, y; };

// ---------------- scratch (no cudaMalloc) ----------------
__device__ float  g_projT[B_*PROJ*K_];     // [b][c][k] : 4 MB
__device__ float  g_part[1024];
__device__ float  g_scale;
__device__ float  g_ypred[NSEQ];
// transformed weights
__device__ float4 g_wp4 [64*64];           // [k4][j]     proj_w
__device__ float4 g_win [NLAYER*32*512];   // [L][k4][j]  inproj
__device__ float4 g_wout[NLAYER*64*128];   // [L][d4][m]  outproj
__device__ float4 g_wx4 [NLAYER*64*40];    // [L][d4][q]  xproj
__device__ float  g_negA[NLAYER*16*256];   // [L][n][d] = -exp(A_log)
__device__ float  g_dtw [NLAYER*8*256];    // [L][r][d]
__device__ float  g_convT[NLAYER*4*256];   // [L][i][d]

// ---------------- helpers ----------------
__device__ __forceinline__ void fma2(ull &d, ull a, ull b) {
    asm("fma.rn.f32x2 %0, %1, %2, %0;" : "+l"(d) : "l"(a), "l"(b));
}
__device__ __forceinline__ float f2sum(ull v) {
    float lo, hi;
    asm("mov.b64 {%0,%1}, %2;" : "=f"(lo), "=f"(hi) : "l"(v));
    return lo + hi;
}
__device__ __forceinline__ float siluf(float x) { return x / (1.0f + __expf(-x)); }
__device__ __forceinline__ float softplusf(float x) {
    return fmaxf(x, 0.0f) + __logf(1.0f + __expf(-fabsf(x)));
}

// =================================================================
// Kernel 0: one-time weight transform (k-interleaved, coalesce-friendly)
// =================================================================
#define TR_TOTAL 141312
__global__ void k_transpose(const float* __restrict__ pw,
                            const float* __restrict__ inw,
                            const float* __restrict__ outw,
                            const float* __restrict__ xw,
                            const float* __restrict__ Alog,
                            const float* __restrict__ dtw,
                            const float* __restrict__ cw) {
    int idx = blockIdx.x*256 + threadIdx.x;
    if (idx < 4096) {                                   // proj_w
        int j = idx >> 6, k4 = idx & 63;
        g_wp4[k4*64 + j] = *(const float4*)(pw + j*DIN + k4*4);
        return;
    }
    idx -= 4096;
    if (idx < 65536) {                                  // inproj
        int jf = idx >> 5, k4 = idx & 31;               // jf = L*512+j
        int L = jf >> 9, j = jf & 511;
        g_win[(L*32 + k4)*512 + j] = *(const float4*)(inw + (size_t)jf*DMODEL + k4*4);
        return;
    }
    idx -= 65536;
    if (idx < 32768) {                                  // outproj
        int mf = idx >> 6, d4 = idx & 63;               // mf = L*128+m
        int L = mf >> 7, m = mf & 127;
        g_wout[(L*64 + d4)*128 + m] = *(const float4*)(outw + (size_t)mf*DINNER + d4*4);
        return;
    }
    idx -= 32768;
    if (idx < 10240) {                                  // xproj
        int qf = idx >> 6, d4 = idx & 63;               // qf = L*40+q
        int L = qf / 40, q = qf % 40;
        g_wx4[(L*64 + d4)*40 + q] = *(const float4*)(xw + (size_t)qf*DINNER + d4*4);
        return;
    }
    idx -= 10240;
    if (idx < 16384) {                                  // -exp(A_log)
        int df = idx >> 4, n = idx & 15;                // df = L*256+d
        int L = df >> 8, d = df & 255;
        g_negA[(L*16 + n)*256 + d] = -expf(Alog[df*16 + n]);
        return;
    }
    idx -= 16384;
    if (idx < 8192) {                                   // dtproj_w
        int df = idx >> 3, r = idx & 7;
        int L = df >> 8, d = df & 255;
        g_dtw[(L*8 + r)*256 + d] = dtw[df*8 + r];
        return;
    }
    idx -= 8192;
    if (idx < 4096) {                                   // conv_w
        int df = idx >> 2, i = idx & 3;
        int L = df >> 8, d = df & 255;
        g_convT[(L*4 + i)*256 + d] = cw[df*4 + i];
    }
}

// =================================================================
// Kernel 1: input projection, 16 rows/block, coalesced weights
// out: g_projT[b][j][k]  (k = position within sequence)
// =================================================================
__global__ void __launch_bounds__(256) k_proj(const float* __restrict__ x,
                                              const float* __restrict__ pb) {
    __shared__ float sx[256*20];     // acts transposed [k][r], stride 20
    __shared__ float red[8];
    int tid = threadIdx.x, bid = blockIdx.x;
    int rowb = bid*16;
    for (int i = tid; i < 16*256; i += 256) {
        int r = i >> 8, k = i & 255;
        sx[k*20 + r] = x[(size_t)(rowb + r)*DIN + k];
    }
    __syncthreads();

    int j = tid & 63, rgrp = tid >> 6;
    float bj = pb[j];
    float a0 = bj, a1 = bj, a2 = bj, a3 = bj;
#pragma unroll 4
    for (int k4 = 0; k4 < 64; k4++) {
        float4 w = g_wp4[k4*64 + j];
        float4 v;
        v = *(const float4*)(sx + (k4*4+0)*20 + rgrp*4);
        a0=fmaf(w.x,v.x,a0); a1=fmaf(w.x,v.y,a1); a2=fmaf(w.x,v.z,a2); a3=fmaf(w.x,v.w,a3);
        v = *(const float4*)(sx + (k4*4+1)*20 + rgrp*4);
        a0=fmaf(w.y,v.x,a0); a1=fmaf(w.y,v.y,a1); a2=fmaf(w.y,v.z,a2); a3=fmaf(w.y,v.w,a3);
        v = *(const float4*)(sx + (k4*4+2)*20 + rgrp*4);
        a0=fmaf(w.z,v.x,a0); a1=fmaf(w.z,v.y,a1); a2=fmaf(w.z,v.z,a2); a3=fmaf(w.z,v.w,a3);
        v = *(const float4*)(sx + (k4*4+3)*20 + rgrp*4);
        a0=fmaf(w.w,v.x,a0); a1=fmaf(w.w,v.y,a1); a2=fmaf(w.w,v.z,a2); a3=fmaf(w.w,v.w,a3);
    }
    a0 = fminf(5.0f, fmaxf(-5.0f, a0));
    a1 = fminf(5.0f, fmaxf(-5.0f, a1));
    a2 = fminf(5.0f, fmaxf(-5.0f, a2));
    a3 = fminf(5.0f, fmaxf(-5.0f, a3));
    int b = rowb >> 7, k0 = (bid & 7) * 16;
    float4 o = make_float4(a0, a1, a2, a3);
    *(float4*)(g_projT + ((size_t)(b*PROJ + j))*K_ + k0 + rgrp*4) = o;

    float s = fabsf(a0)+fabsf(a1)+fabsf(a2)+fabsf(a3);
#pragma unroll
    for (int off = 16; off; off >>= 1) s += __shfl_xor_sync(0xffffffffu, s, off);
    if ((tid & 31) == 0) red[tid >> 5] = s;
    __syncthreads();
    if (tid == 0) {
        float t = 0.0f;
#pragma unroll
        for (int i = 0; i < 8; i++) t += red[i];
        g_part[bid] = t;
    }
}

// =================================================================
// Kernel 2: reduce abs partials -> g_scale
// =================================================================
__global__ void k_reduce() {
    int tid = threadIdx.x;           // 256
    __shared__ float red[8];
    float s = 0.0f;
    for (int i = tid; i < 1024; i += 256) s += g_part[i];
#pragma unroll
    for (int o = 16; o; o >>= 1) s += __shfl_xor_sync(0xffffffffu, s, o);
    if ((tid & 31) == 0) red[tid >> 5] = s;
    __syncthreads();
    if (tid == 0) {
        float t = 0.0f;
#pragma unroll
        for (int i = 0; i < 8; i++) t += red[i];
        g_scale = t * (1.0f/(float)(B_*K_*PROJ)) + 1e-6f;
    }
}

// =================================================================
// Mega-kernel: one block per sequence
// =================================================================
#define OFF_H    0
#define OFF_HN   4096
#define OFF_XR   8192       // 32 x 512 : [xc | res] -> [ys | partials]
#define OFF_DBL  24576      // 32 x 40
#define OFF_XN   25856      // 132 (+pad)
#define OFF_RED  25992
#define OFF_MISC 26024
#define SMEM_FLOATS 26032   // 104128 B -> 2 blocks/SM

__device__ __forceinline__ float block_reduce256(float v, float* red) {
#pragma unroll
    for (int o = 16; o; o >>= 1) v += __shfl_xor_sync(0xffffffffu, v, o);
    int wid = threadIdx.x >> 5;
    if ((threadIdx.x & 31) == 0) red[wid] = v;
    __syncthreads();
    if (threadIdx.x == 0) {
        float t = 0.0f;
#pragma unroll
        for (int i = 0; i < 8; i++) t += red[i];
        red[0] = t;
    }
    __syncthreads();
    float r = red[0];
    __syncthreads();
    return r;
}

__global__ void __launch_bounds__(256, 2) k_mamba(
    const float* __restrict__ emb_w,   const float* __restrict__ emb_b,
    const float* __restrict__ norm_w,  const float* __restrict__ conv_b,
    const float* __restrict__ dtproj_b,const float* __restrict__ D_p,
    const float* __restrict__ normf_w, const float* __restrict__ headb_w,
    const float* __restrict__ headb_b)
{
    extern __shared__ float sm[];
    float* sh    = sm + OFF_H;
    float* shn   = sm + OFF_HN;
    float* sxr   = sm + OFF_XR;
    float* sdbl  = sm + OFF_DBL;
    float* sxn   = sm + OFF_XN;
    float* sred  = sm + OFF_RED;
    float* smisc = sm + OFF_MISC;

    const int tid = threadIdx.x;
    const int seq = blockIdx.x;
    const int b   = seq >> 6;
    const int c   = seq & 63;

    // -------- Phase A: scale + instance norm over K (coalesced read) ----
    const float inv_s = 1.0f / g_scale;
    float val = 0.0f;
    if (tid < K_) val = g_projT[((size_t)(b*PROJ + c))*K_ + tid] * inv_s;
    float su = block_reduce256(tid < K_ ? val : 0.0f, sred);
    float sq = block_reduce256(tid < K_ ? val*val : 0.0f, sred);
    float mu  = su * (1.0f/(float)K_);
    float var = sq * (1.0f/(float)K_) - mu*mu;
    float sd  = sqrtf(var + 1e-5f);
    float rsd = 1.0f / sd;
    if (tid < K_) sxn[tid] = (val - mu) * rsd;
    if (tid == 0) { smisc[0] = mu; smisc[1] = sd; }
    __syncthreads();
    if (tid < STRIDE) sxn[K_ + tid] = sxn[K_ - 1];
    __syncthreads();

    // -------- Phase B: patch embedding -> h --------
    {
        int m  = tid & 127;
        int n0 = tid >> 7;
        float4 e0 = *(const float4*)(emb_w + m*PLEN);
        float4 e1 = *(const float4*)(emb_w + m*PLEN + 4);
        float  eb = emb_b[m];
        for (int n = n0; n < NPATCH; n += 2) {
            const float* xp = sxn + n*STRIDE;
            float v = eb;
            v = fmaf(e0.x, xp[0], v); v = fmaf(e0.y, xp[1], v);
            v = fmaf(e0.z, xp[2], v); v = fmaf(e0.w, xp[3], v);
            v = fmaf(e1.x, xp[4], v); v = fmaf(e1.y, xp[5], v);
            v = fmaf(e1.z, xp[6], v); v = fmaf(e1.w, xp[7], v);
            sh[n*DMODEL + m] = v;
        }
    }
    __syncthreads();

    // -------- Phase C: 4 Mamba layers --------
    for (int L = 0; L < NLAYER; L++) {
        // 1. rmsnorm(h)*norm_w -> hn
        {
            int wid = tid >> 5, lane = tid & 31;
            float4 wv4 = *(const float4*)(norm_w + L*DMODEL + lane*4);
#pragma unroll
            for (int r = wid*4; r < wid*4 + 4; r++) {
                float4 hv = *(const float4*)(sh + r*DMODEL + lane*4);
                float ss = hv.x*hv.x + hv.y*hv.y + hv.z*hv.z + hv.w*hv.w;
#pragma unroll
                for (int o = 16; o; o >>= 1) ss += __shfl_xor_sync(0xffffffffu, ss, o);
                float rms = rsqrtf(ss*(1.0f/(float)DMODEL) + 1e-5f);
                float4 ov;
                ov.x = hv.x*rms*wv4.x; ov.y = hv.y*rms*wv4.y;
                ov.z = hv.z*rms*wv4.z; ov.w = hv.w*rms*wv4.w;
                *(float4*)(shn + r*DMODEL + lane*4) = ov;
            }
        }
        __syncthreads();

        // 2. inproj: coalesced weight LDG + broadcast LDS + FFMA2
        {
            const ull2* Wb = (const ull2*)(g_win + (size_t)L*32*512);
#pragma unroll 1
            for (int jj = 0; jj < 2; jj++) {
                int j = tid + jj*256;
                ull acc[NPATCH];
#pragma unroll
                for (int t = 0; t < NPATCH; t++) acc[t] = 0ULL;
                ull2 w = Wb[j];
#pragma unroll 1
                for (int k4 = 0; k4 < 32; k4++) {
                    ull2 wc = w;
                    int nk = (k4 < 31) ? k4 + 1 : 31;
                    w = Wb[nk*512 + j];
                    const float* ap = shn + k4*4;
#pragma unroll
                    for (int t = 0; t < NPATCH; t++) {
                        ull2 a = *(const ull2*)(ap + t*DMODEL);
                        fma2(acc[t], wc.x, a.x);
                        fma2(acc[t], wc.y, a.y);
                    }
                }
#pragma unroll
                for (int t = 0; t < NPATCH; t++) sxr[t*512 + j] = f2sum(acc[t]);
            }
        }
        __syncthreads();

        // 3. depthwise conv(4) + bias + silu, in place
        {
            int d = tid;
            float w0 = g_convT[(L*4+0)*256 + d];
            float w1 = g_convT[(L*4+1)*256 + d];
            float w2 = g_convT[(L*4+2)*256 + d];
            float w3 = g_convT[(L*4+3)*256 + d];
            float cb = conv_b[L*DINNER + d];
            float x0 = 0.0f, x1 = 0.0f, x2 = 0.0f;
#pragma unroll
            for (int t = 0; t < NPATCH; t++) {
                float xt = sxr[t*512 + d];
                float o = fmaf(w0, x0, fmaf(w1, x1, fmaf(w2, x2, fmaf(w3, xt, cb))));
                sxr[t*512 + d] = siluf(o);
                x0 = x1; x1 = x2; x2 = xt;
            }
        }
        __syncthreads();

        // 4. xproj: warp owns 4 t-rows, lanes own q (q and q+32)
        {
            int wid = tid >> 5, lane = tid & 31;
            int t0 = wid * 4;
            bool hasB = lane < 8;
            int q2 = 32 + lane;
            const ull2* Wb = (const ull2*)(g_wx4 + (size_t)L*64*40);
            ull accA[4], accB[4];
#pragma unroll
            for (int t = 0; t < 4; t++) { accA[t] = 0ULL; accB[t] = 0ULL; }
#pragma unroll 2
            for (int d4 = 0; d4 < 64; d4++) {
                ull2 w1 = Wb[d4*40 + lane];
                ull2 w2 = hasB ? Wb[d4*40 + q2] : w1;
#pragma unroll
                for (int t = 0; t < 4; t++) {
                    ull2 a = *(const ull2*)(sxr + (t0+t)*512 + d4*4);
                    fma2(accA[t], w1.x, a.x); fma2(accA[t], w1.y, a.y);
                    fma2(accB[t], w2.x, a.x); fma2(accB[t], w2.y, a.y);
                }
            }
#pragma unroll
            for (int t = 0; t < 4; t++) {
                sdbl[(t0+t)*40 + lane] = f2sum(accA[t]);
                if (hasB) sdbl[(t0+t)*40 + q2] = f2sum(accB[t]);
            }
        }
        __syncthreads();

        // 5. selective scan (thread d owns channel d)
        {
            int d = tid;
            float dw[DTRANK];
#pragma unroll
            for (int r = 0; r < DTRANK; r++) dw[r] = g_dtw[(L*8 + r)*256 + d];
            float dtb = dtproj_b[L*DINNER + d];
            float Dp  = D_p[L*DINNER + d];
            float nA[DSTATE];
#pragma unroll
            for (int n = 0; n < DSTATE; n++) nA[n] = g_negA[(L*16 + n)*256 + d];
            float st[DSTATE];
#pragma unroll
            for (int n = 0; n < DSTATE; n++) st[n] = 0.0f;

            for (int t = 0; t < NPATCH; t++) {
                const float* db = sdbl + t*40;
                float dtv = dtb;
#pragma unroll
                for (int r = 0; r < DTRANK; r++) dtv = fmaf(dw[r], db[r], dtv);
                dtv = softplusf(dtv);

                float u = sxr[t*512 + d];
                float du = dtv * u;
                float y = 0.0f;
#pragma unroll
                for (int n = 0; n < DSTATE; n++) {
                    float dA = __expf(dtv * nA[n]);
                    st[n] = fmaf(st[n], dA, du * db[8+n]);
                    y = fmaf(st[n], db[24+n], y);
                }
                y = fmaf(u, Dp, y);
                float rv = sxr[t*512 + DINNER + d];
                sxr[t*512 + d] = y * siluf(rv);
            }
        }
        __syncthreads();

        // 6. outproj: coalesced weight LDG + broadcast LDS + FFMA2
        {
            int m = tid & 127, half = tid >> 7;
            const ull2* Wb = (const ull2*)(g_wout + (size_t)L*64*128);
            int d40 = half * 32;
            ull acc[NPATCH];
#pragma unroll
            for (int t = 0; t < NPATCH; t++) acc[t] = 0ULL;
            ull2 w = Wb[d40*128 + m];
#pragma unroll 1
            for (int d4 = 0; d4 < 32; d4++) {
                ull2 wc = w;
                int nd = (d4 < 31) ? d4 + 1 : 31;
                w = Wb[(d40 + nd)*128 + m];
                const float* ap = sxr + half*128 + d4*4;
#pragma unroll
                for (int t = 0; t < NPATCH; t++) {
                    ull2 a = *(const ull2*)(ap + t*512);
                    fma2(acc[t], wc.x, a.x);
                    fma2(acc[t], wc.y, a.y);
                }
            }
#pragma unroll
            for (int t = 0; t < NPATCH; t++)
                sxr[t*512 + DINNER + half*128 + m] = f2sum(acc[t]);
        }
        __syncthreads();
        for (int o = tid; o < NPATCH*DMODEL; o += 256) {
            int t = o >> 7, m = o & 127;
            sh[o] += sxr[t*512 + DINNER + m] + sxr[t*512 + DINNER + 128 + m];
        }
        __syncthreads();
    }

    // -------- Phase D: final rmsnorm + headb dot + denorm --------
    {
        int wid = tid >> 5, lane = tid & 31;
        float4 wv4 = *(const float4*)(normf_w + lane*4);
#pragma unroll
        for (int r = wid*4; r < wid*4 + 4; r++) {
            float4 hv = *(const float4*)(sh + r*DMODEL + lane*4);
            float ss = hv.x*hv.x + hv.y*hv.y + hv.z*hv.z + hv.w*hv.w;
#pragma unroll
            for (int o = 16; o; o >>= 1) ss += __shfl_xor_sync(0xffffffffu, ss, o);
            float rms = rsqrtf(ss*(1.0f/(float)DMODEL) + 1e-5f);
            float4 ov;
            ov.x = hv.x*rms*wv4.x; ov.y = hv.y*rms*wv4.y;
            ov.z = hv.z*rms*wv4.z; ov.w = hv.w*rms*wv4.w;
            *(float4*)(shn + r*DMODEL + lane*4) = ov;
        }
    }
    __syncthreads();

    float loc = 0.0f;
    for (int o = tid; o < NPATCH*DMODEL; o += 256) loc += shn[o]*headb_w[o];
    float tot = block_reduce256(loc, sred);
    if (tid == 0) {
        float yv = tot + headb_b[0];
        g_ypred[seq] = yv * smisc[1] + smisc[0];
    }
}

// =================================================================
// Kernel 4: final head  (128,64) @ (64,2)
// =================================================================
__global__ void k_head(const float* __restrict__ head_w,
                       const float* __restrict__ head_b,
                       float* __restrict__ out) {
    int tid = threadIdx.x;          // 256 = 128 b x 2 o
    int b = tid >> 1, o = tid & 1;
    float acc = head_b[o];
    const float* w = head_w + o*PROJ;
#pragma unroll 8
    for (int c = 0; c < PROJ; c++) acc = fmaf(g_ypred[b*PROJ + c], w[c], acc);
    out[b*2 + o] = acc;
}

// =================================================================
// launch
// =================================================================
extern "C" void kernel_launch(void* const* d_in, const int* in_sizes, int n_in,
                              void* d_out, int out_size) {
    const float* x         = (const float*)d_in[0];
    const float* proj_w    = (const float*)d_in[1];
    const float* proj_b    = (const float*)d_in[2];
    const float* emb_w     = (const float*)d_in[3];
    const float* emb_b     = (const float*)d_in[4];
    const float* norm_w    = (const float*)d_in[5];
    const float* inproj_w  = (const float*)d_in[6];
    const float* conv_w    = (const float*)d_in[7];
    const float* conv_b    = (const float*)d_in[8];
    const float* xproj_w   = (const float*)d_in[9];
    const float* dtproj_w  = (const float*)d_in[10];
    const float* dtproj_b  = (const float*)d_in[11];
    const float* A_log     = (const float*)d_in[12];
    const float* D_p       = (const float*)d_in[13];
    const float* outproj_w = (const float*)d_in[14];
    const float* normf_w   = (const float*)d_in[15];
    const float* headb_w   = (const float*)d_in[16];
    const float* headb_b   = (const float*)d_in[17];
    const float* head_w    = (const float*)d_in[18];
    const float* head_b    = (const float*)d_in[19];

    cudaFuncSetAttribute(k_mamba, cudaFuncAttributeMaxDynamicSharedMemorySize,
                         SMEM_FLOATS * sizeof(float));

    k_transpose<<<(TR_TOTAL + 255)/256, 256>>>(proj_w, inproj_w, outproj_w,
                                               xproj_w, A_log, dtproj_w, conv_w);
    k_proj<<<(B_*K_)/16, 256>>>(x, proj_b);
    k_reduce<<<1, 256>>>();
    k_mamba<<<NSEQ, 256, SMEM_FLOATS * sizeof(float)>>>(
        emb_w, emb_b, norm_w, conv_b, dtproj_b, D_p, normf_w, headb_w, headb_b);
    k_head<<<1, 256>>>(head_w, head_b, (float*)d_out);
}

// round 5
// speedup vs baseline: 2.1729x; 1.0212x over previous
#include <cuda_runtime.h>
#include <math.h>

// ---------------- dims ----------------
#define B_      128
#define K_      128
#define DIN     256
#define PROJ    64
#define DMODEL  128
#define NLAYER  4
#define PLEN    8
#define STRIDE  4
#define DINNER  256
#define DSTATE  16
#define DTRANK  8
#define NPATCH  32
#define NSEQ    (B_*PROJ)        // 8192

typedef unsigned long long ull;
struct __align__(16) ull2 { ull x, y; };

// ---------------- scratch (no cudaMalloc) ----------------
__device__ float  g_projT[B_*PROJ*K_];     // [b][c][k] : 4 MB
__device__ float  g_part[1024];
__device__ float  g_scale;
__device__ float  g_ypred[NSEQ];
// transformed weights
__device__ float4 g_wp4 [64*64];           // [k4][j]     proj_w
__device__ float4 g_win [NLAYER*32*512];   // [L][k4][j]  inproj
__device__ float4 g_wout[NLAYER*64*128];   // [L][d4][m]  outproj
__device__ float4 g_wx4 [NLAYER*64*40];    // [L][d4][q]  xproj
__device__ float  g_negA[NLAYER*16*256];   // [L][n][d] = -exp(A_log)
__device__ float  g_dtw [NLAYER*8*256];    // [L][r][d]
__device__ float  g_convT[NLAYER*4*256];   // [L][i][d]

// ---------------- helpers ----------------
__device__ __forceinline__ void fma2(ull &d, ull a, ull b) {
    asm("fma.rn.f32x2 %0, %1, %2, %0;" : "+l"(d) : "l"(a), "l"(b));
}
__device__ __forceinline__ float f2sum(ull v) {
    float lo, hi;
    asm("mov.b64 {%0,%1}, %2;" : "=f"(lo), "=f"(hi) : "l"(v));
    return lo + hi;
}
__device__ __forceinline__ float siluf(float x) { return x / (1.0f + __expf(-x)); }
__device__ __forceinline__ float softplusf(float x) {
    return fmaxf(x, 0.0f) + __logf(1.0f + __expf(-fabsf(x)));
}

// =================================================================
// Kernel 0: one-time weight transform (k-interleaved, coalesce-friendly)
// =================================================================
#define TR_TOTAL 141312
__global__ void k_transpose(const float* __restrict__ pw,
                            const float* __restrict__ inw,
                            const float* __restrict__ outw,
                            const float* __restrict__ xw,
                            const float* __restrict__ Alog,
                            const float* __restrict__ dtw,
                            const float* __restrict__ cw) {
    int idx = blockIdx.x*256 + threadIdx.x;
    if (idx < 4096) {                                   // proj_w
        int j = idx >> 6, k4 = idx & 63;
        g_wp4[k4*64 + j] = *(const float4*)(pw + j*DIN + k4*4);
        return;
    }
    idx -= 4096;
    if (idx < 65536) {                                  // inproj
        int jf = idx >> 5, k4 = idx & 31;               // jf = L*512+j
        int L = jf >> 9, j = jf & 511;
        g_win[(L*32 + k4)*512 + j] = *(const float4*)(inw + (size_t)jf*DMODEL + k4*4);
        return;
    }
    idx -= 65536;
    if (idx < 32768) {                                  // outproj
        int mf = idx >> 6, d4 = idx & 63;               // mf = L*128+m
        int L = mf >> 7, m = mf & 127;
        g_wout[(L*64 + d4)*128 + m] = *(const float4*)(outw + (size_t)mf*DINNER + d4*4);
        return;
    }
    idx -= 32768;
    if (idx < 10240) {                                  // xproj
        int qf = idx >> 6, d4 = idx & 63;               // qf = L*40+q
        int L = qf / 40, q = qf % 40;
        g_wx4[(L*64 + d4)*40 + q] = *(const float4*)(xw + (size_t)qf*DINNER + d4*4);
        return;
    }
    idx -= 10240;
    if (idx < 16384) {                                  // -exp(A_log)
        int df = idx >> 4, n = idx & 15;                // df = L*256+d
        int L = df >> 8, d = df & 255;
        g_negA[(L*16 + n)*256 + d] = -expf(Alog[df*16 + n]);
        return;
    }
    idx -= 16384;
    if (idx < 8192) {                                   // dtproj_w
        int df = idx >> 3, r = idx & 7;
        int L = df >> 8, d = df & 255;
        g_dtw[(L*8 + r)*256 + d] = dtw[df*8 + r];
        return;
    }
    idx -= 8192;
    if (idx < 4096) {                                   // conv_w
        int df = idx >> 2, i = idx & 3;
        int L = df >> 8, d = df & 255;
        g_convT[(L*4 + i)*256 + d] = cw[df*4 + i];
    }
}

// =================================================================
// Kernel 1: input projection, 16 rows/block, coalesced weights
// =================================================================
__global__ void __launch_bounds__(256) k_proj(const float* __restrict__ x,
                                              const float* __restrict__ pb) {
    __shared__ float sx[256*20];     // acts transposed [k][r], stride 20
    __shared__ float red[8];
    int tid = threadIdx.x, bid = blockIdx.x;
    int rowb = bid*16;
    for (int i = tid; i < 16*256; i += 256) {
        int r = i >> 8, k = i & 255;
        sx[k*20 + r] = x[(size_t)(rowb + r)*DIN + k];
    }
    __syncthreads();

    int j = tid & 63, rgrp = tid >> 6;
    float bj = pb[j];
    float a0 = bj, a1 = bj, a2 = bj, a3 = bj;
#pragma unroll 4
    for (int k4 = 0; k4 < 64; k4++) {
        float4 w = g_wp4[k4*64 + j];
        float4 v;
        v = *(const float4*)(sx + (k4*4+0)*20 + rgrp*4);
        a0=fmaf(w.x,v.x,a0); a1=fmaf(w.x,v.y,a1); a2=fmaf(w.x,v.z,a2); a3=fmaf(w.x,v.w,a3);
        v = *(const float4*)(sx + (k4*4+1)*20 + rgrp*4);
        a0=fmaf(w.y,v.x,a0); a1=fmaf(w.y,v.y,a1); a2=fmaf(w.y,v.z,a2); a3=fmaf(w.y,v.w,a3);
        v = *(const float4*)(sx + (k4*4+2)*20 + rgrp*4);
        a0=fmaf(w.z,v.x,a0); a1=fmaf(w.z,v.y,a1); a2=fmaf(w.z,v.z,a2); a3=fmaf(w.z,v.w,a3);
        v = *(const float4*)(sx + (k4*4+3)*20 + rgrp*4);
        a0=fmaf(w.w,v.x,a0); a1=fmaf(w.w,v.y,a1); a2=fmaf(w.w,v.z,a2); a3=fmaf(w.w,v.w,a3);
    }
    a0 = fminf(5.0f, fmaxf(-5.0f, a0));
    a1 = fminf(5.0f, fmaxf(-5.0f, a1));
    a2 = fminf(5.0f, fmaxf(-5.0f, a2));
    a3 = fminf(5.0f, fmaxf(-5.0f, a3));
    int b = rowb >> 7, k0 = (bid & 7) * 16;
    float4 o = make_float4(a0, a1, a2, a3);
    *(float4*)(g_projT + ((size_t)(b*PROJ + j))*K_ + k0 + rgrp*4) = o;

    float s = fabsf(a0)+fabsf(a1)+fabsf(a2)+fabsf(a3);
#pragma unroll
    for (int off = 16; off; off >>= 1) s += __shfl_xor_sync(0xffffffffu, s, off);
    if ((tid & 31) == 0) red[tid >> 5] = s;
    __syncthreads();
    if (tid == 0) {
        float t = 0.0f;
#pragma unroll
        for (int i = 0; i < 8; i++) t += red[i];
        g_part[bid] = t;
    }
}

// =================================================================
// Kernel 2: reduce abs partials -> g_scale
// =================================================================
__global__ void k_reduce() {
    int tid = threadIdx.x;           // 256
    __shared__ float red[8];
    float s = 0.0f;
    for (int i = tid; i < 1024; i += 256) s += g_part[i];
#pragma unroll
    for (int o = 16; o; o >>= 1) s += __shfl_xor_sync(0xffffffffu, s, o);
    if ((tid & 31) == 0) red[tid >> 5] = s;
    __syncthreads();
    if (tid == 0) {
        float t = 0.0f;
#pragma unroll
        for (int i = 0; i < 8; i++) t += red[i];
        g_scale = t * (1.0f/(float)(B_*K_*PROJ)) + 1e-6f;
    }
}

// =================================================================
// Mega-kernel: one block per sequence
// =================================================================
#define OFF_H    0
#define OFF_HN   4096
#define OFF_XR   8192       // 32 x 512 : [xc | res] -> [ys | outproj result]
#define OFF_DBL  24576      // 32 x 40
#define OFF_XN   25856      // 132 (+pad)
#define OFF_RED  25992
#define OFF_MISC 26024
#define SMEM_FLOATS 26032   // 104128 B -> 2 blocks/SM

__device__ __forceinline__ float block_reduce256(float v, float* red) {
#pragma unroll
    for (int o = 16; o; o >>= 1) v += __shfl_xor_sync(0xffffffffu, v, o);
    int wid = threadIdx.x >> 5;
    if ((threadIdx.x & 31) == 0) red[wid] = v;
    __syncthreads();
    if (threadIdx.x == 0) {
        float t = 0.0f;
#pragma unroll
        for (int i = 0; i < 8; i++) t += red[i];
        red[0] = t;
    }
    __syncthreads();
    float r = red[0];
    __syncthreads();
    return r;
}

__global__ void __launch_bounds__(256, 2) k_mamba(
    const float* __restrict__ emb_w,   const float* __restrict__ emb_b,
    const float* __restrict__ norm_w,  const float* __restrict__ conv_b,
    const float* __restrict__ dtproj_b,const float* __restrict__ D_p,
    const float* __restrict__ normf_w, const float* __restrict__ headb_w,
    const float* __restrict__ headb_b)
{
    extern __shared__ float sm[];
    float* sh    = sm + OFF_H;
    float* shn   = sm + OFF_HN;
    float* sxr   = sm + OFF_XR;
    float* sdbl  = sm + OFF_DBL;
    float* sxn   = sm + OFF_XN;
    float* sred  = sm + OFF_RED;
    float* smisc = sm + OFF_MISC;

    const int tid = threadIdx.x;
    const int seq = blockIdx.x;
    const int b   = seq >> 6;
    const int c   = seq & 63;

    // -------- Phase A: scale + instance norm over K --------
    const float inv_s = 1.0f / g_scale;
    float val = 0.0f;
    if (tid < K_) val = g_projT[((size_t)(b*PROJ + c))*K_ + tid] * inv_s;
    float su = block_reduce256(tid < K_ ? val : 0.0f, sred);
    float sq = block_reduce256(tid < K_ ? val*val : 0.0f, sred);
    float mu  = su * (1.0f/(float)K_);
    float var = sq * (1.0f/(float)K_) - mu*mu;
    float sd  = sqrtf(var + 1e-5f);
    float rsd = 1.0f / sd;
    if (tid < K_) sxn[tid] = (val - mu) * rsd;
    if (tid == 0) { smisc[0] = mu; smisc[1] = sd; }
    __syncthreads();
    if (tid < STRIDE) sxn[K_ + tid] = sxn[K_ - 1];
    __syncthreads();

    // -------- Phase B: patch embedding -> h --------
    {
        int m  = tid & 127;
        int n0 = tid >> 7;
        float4 e0 = *(const float4*)(emb_w + m*PLEN);
        float4 e1 = *(const float4*)(emb_w + m*PLEN + 4);
        float  eb = emb_b[m];
        for (int n = n0; n < NPATCH; n += 2) {
            const float* xp = sxn + n*STRIDE;
            float v = eb;
            v = fmaf(e0.x, xp[0], v); v = fmaf(e0.y, xp[1], v);
            v = fmaf(e0.z, xp[2], v); v = fmaf(e0.w, xp[3], v);
            v = fmaf(e1.x, xp[4], v); v = fmaf(e1.y, xp[5], v);
            v = fmaf(e1.z, xp[6], v); v = fmaf(e1.w, xp[7], v);
            sh[n*DMODEL + m] = v;
        }
    }
    __syncthreads();

    // -------- Phase C: 4 Mamba layers --------
    for (int L = 0; L < NLAYER; L++) {
        // 1. rmsnorm(h)*norm_w -> hn
        {
            int wid = tid >> 5, lane = tid & 31;
            float4 wv4 = *(const float4*)(norm_w + L*DMODEL + lane*4);
#pragma unroll
            for (int r = wid*4; r < wid*4 + 4; r++) {
                float4 hv = *(const float4*)(sh + r*DMODEL + lane*4);
                float ss = hv.x*hv.x + hv.y*hv.y + hv.z*hv.z + hv.w*hv.w;
#pragma unroll
                for (int o = 16; o; o >>= 1) ss += __shfl_xor_sync(0xffffffffu, ss, o);
                float rms = rsqrtf(ss*(1.0f/(float)DMODEL) + 1e-5f);
                float4 ov;
                ov.x = hv.x*rms*wv4.x; ov.y = hv.y*rms*wv4.y;
                ov.z = hv.z*rms*wv4.z; ov.w = hv.w*rms*wv4.w;
                *(float4*)(shn + r*DMODEL + lane*4) = ov;
            }
        }
        __syncthreads();

        // 2. inproj: 2-j register tile (j, j+256), t in halves of 16
        //    ratio 4 FFMA2 per activation LDS
        {
            const ull2* Wb = (const ull2*)(g_win + (size_t)L*32*512);
#pragma unroll 1
            for (int th = 0; th < 2; th++) {
                const int tbase = th*16;
                ull acc0[16], acc1[16];
#pragma unroll
                for (int t = 0; t < 16; t++) { acc0[t] = 0ULL; acc1[t] = 0ULL; }
#pragma unroll 1
                for (int k4 = 0; k4 < 32; k4++) {
                    ull2 w0 = Wb[k4*512 + tid];
                    ull2 w1 = Wb[k4*512 + tid + 256];
                    const float* ap = shn + tbase*DMODEL + k4*4;
#pragma unroll
                    for (int t = 0; t < 16; t++) {
                        ull2 a = *(const ull2*)(ap + t*DMODEL);
                        fma2(acc0[t], w0.x, a.x); fma2(acc0[t], w0.y, a.y);
                        fma2(acc1[t], w1.x, a.x); fma2(acc1[t], w1.y, a.y);
                    }
                }
#pragma unroll
                for (int t = 0; t < 16; t++) {
                    sxr[(tbase+t)*512 + tid]       = f2sum(acc0[t]);
                    sxr[(tbase+t)*512 + tid + 256] = f2sum(acc1[t]);
                }
            }
        }
        __syncthreads();

        // 3. depthwise conv(4) + bias + silu, in place
        {
            int d = tid;
            float w0 = g_convT[(L*4+0)*256 + d];
            float w1 = g_convT[(L*4+1)*256 + d];
            float w2 = g_convT[(L*4+2)*256 + d];
            float w3 = g_convT[(L*4+3)*256 + d];
            float cb = conv_b[L*DINNER + d];
            float x0 = 0.0f, x1 = 0.0f, x2 = 0.0f;
#pragma unroll
            for (int t = 0; t < NPATCH; t++) {
                float xt = sxr[t*512 + d];
                float o = fmaf(w0, x0, fmaf(w1, x1, fmaf(w2, x2, fmaf(w3, xt, cb))));
                sxr[t*512 + d] = siluf(o);
                x0 = x1; x1 = x2; x2 = xt;
            }
        }
        __syncthreads();

        // 4. xproj: warp owns 4 t-rows, lanes own q (q and q+32)
        {
            int wid = tid >> 5, lane = tid & 31;
            int t0 = wid * 4;
            bool hasB = lane < 8;
            int q2 = 32 + lane;
            const ull2* Wb = (const ull2*)(g_wx4 + (size_t)L*64*40);
            ull accA[4], accB[4];
#pragma unroll
            for (int t = 0; t < 4; t++) { accA[t] = 0ULL; accB[t] = 0ULL; }
#pragma unroll 2
            for (int d4 = 0; d4 < 64; d4++) {
                ull2 w1 = Wb[d4*40 + lane];
                ull2 w2 = hasB ? Wb[d4*40 + q2] : w1;
#pragma unroll
                for (int t = 0; t < 4; t++) {
                    ull2 a = *(const ull2*)(sxr + (t0+t)*512 + d4*4);
                    fma2(accA[t], w1.x, a.x); fma2(accA[t], w1.y, a.y);
                    fma2(accB[t], w2.x, a.x); fma2(accB[t], w2.y, a.y);
                }
            }
#pragma unroll
            for (int t = 0; t < 4; t++) {
                sdbl[(t0+t)*40 + lane] = f2sum(accA[t]);
                if (hasB) sdbl[(t0+t)*40 + q2] = f2sum(accB[t]);
            }
        }
        __syncthreads();

        // 5. selective scan (thread d owns channel d)
        {
            int d = tid;
            float dw[DTRANK];
#pragma unroll
            for (int r = 0; r < DTRANK; r++) dw[r] = g_dtw[(L*8 + r)*256 + d];
            float dtb = dtproj_b[L*DINNER + d];
            float Dp  = D_p[L*DINNER + d];
            float nA[DSTATE];
#pragma unroll
            for (int n = 0; n < DSTATE; n++) nA[n] = g_negA[(L*16 + n)*256 + d];
            float st[DSTATE];
#pragma unroll
            for (int n = 0; n < DSTATE; n++) st[n] = 0.0f;

            for (int t = 0; t < NPATCH; t++) {
                const float* db = sdbl + t*40;
                float dtv = dtb;
#pragma unroll
                for (int r = 0; r < DTRANK; r++) dtv = fmaf(dw[r], db[r], dtv);
                dtv = softplusf(dtv);

                float u = sxr[t*512 + d];
                float du = dtv * u;
                float y = 0.0f;
#pragma unroll
                for (int n = 0; n < DSTATE; n++) {
                    float dA = __expf(dtv * nA[n]);
                    st[n] = fmaf(st[n], dA, du * db[8+n]);
                    y = fmaf(st[n], db[24+n], y);
                }
                y = fmaf(u, Dp, y);
                float rv = sxr[t*512 + DINNER + d];
                sxr[t*512 + d] = y * siluf(rv);
            }
        }
        __syncthreads();

        // 6. outproj: 2-m register tile (m2, m2+64), full d range, 8 t per thread
        {
            int m2 = tid & 63, tq = tid >> 6;      // tq in 0..3 -> 8 t each
            int tb = tq * 8;
            const ull2* Wb = (const ull2*)(g_wout + (size_t)L*64*128);
            ull acc0[8], acc1[8];
#pragma unroll
            for (int t = 0; t < 8; t++) { acc0[t] = 0ULL; acc1[t] = 0ULL; }
#pragma unroll 1
            for (int d4 = 0; d4 < 64; d4++) {
                ull2 w0 = Wb[d4*128 + m2];
                ull2 w1 = Wb[d4*128 + m2 + 64];
                const float* ap = sxr + tb*512 + d4*4;
#pragma unroll
                for (int t = 0; t < 8; t++) {
                    ull2 a = *(const ull2*)(ap + t*512);
                    fma2(acc0[t], w0.x, a.x); fma2(acc0[t], w0.y, a.y);
                    fma2(acc1[t], w1.x, a.x); fma2(acc1[t], w1.y, a.y);
                }
            }
#pragma unroll
            for (int t = 0; t < 8; t++) {
                sxr[(tb+t)*512 + DINNER + m2]      = f2sum(acc0[t]);
                sxr[(tb+t)*512 + DINNER + 64 + m2] = f2sum(acc1[t]);
            }
        }
        __syncthreads();
        for (int o = tid; o < NPATCH*DMODEL; o += 256) {
            int t = o >> 7, m = o & 127;
            sh[o] += sxr[t*512 + DINNER + m];
        }
        __syncthreads();
    }

    // -------- Phase D: final rmsnorm + headb dot + denorm --------
    {
        int wid = tid >> 5, lane = tid & 31;
        float4 wv4 = *(const float4*)(normf_w + lane*4);
#pragma unroll
        for (int r = wid*4; r < wid*4 + 4; r++) {
            float4 hv = *(const float4*)(sh + r*DMODEL + lane*4);
            float ss = hv.x*hv.x + hv.y*hv.y + hv.z*hv.z + hv.w*hv.w;
#pragma unroll
            for (int o = 16; o; o >>= 1) ss += __shfl_xor_sync(0xffffffffu, ss, o);
            float rms = rsqrtf(ss*(1.0f/(float)DMODEL) + 1e-5f);
            float4 ov;
            ov.x = hv.x*rms*wv4.x; ov.y = hv.y*rms*wv4.y;
            ov.z = hv.z*rms*wv4.z; ov.w = hv.w*rms*wv4.w;
            *(float4*)(shn + r*DMODEL + lane*4) = ov;
        }
    }
    __syncthreads();

    float loc = 0.0f;
    for (int o = tid; o < NPATCH*DMODEL; o += 256) loc += shn[o]*headb_w[o];
    float tot = block_reduce256(loc, sred);
    if (tid == 0) {
        float yv = tot + headb_b[0];
        g_ypred[seq] = yv * smisc[1] + smisc[0];
    }
}

// =================================================================
// Kernel 4: final head  (128,64) @ (64,2)
// =================================================================
__global__ void k_head(const float* __restrict__ head_w,
                       const float* __restrict__ head_b,
                       float* __restrict__ out) {
    int tid = threadIdx.x;          // 256 = 128 b x 2 o
    int b = tid >> 1, o = tid & 1;
    float acc = head_b[o];
    const float* w = head_w + o*PROJ;
#pragma unroll 8
    for (int c = 0; c < PROJ; c++) acc = fmaf(g_ypred[b*PROJ + c], w[c], acc);
    out[b*2 + o] = acc;
}

// =================================================================
// launch
// =================================================================
extern "C" void kernel_launch(void* const* d_in, const int* in_sizes, int n_in,
                              void* d_out, int out_size) {
    const float* x         = (const float*)d_in[0];
    const float* proj_w    = (const float*)d_in[1];
    const float* proj_b    = (const float*)d_in[2];
    const float* emb_w     = (const float*)d_in[3];
    const float* emb_b     = (const float*)d_in[4];
    const float* norm_w    = (const float*)d_in[5];
    const float* inproj_w  = (const float*)d_in[6];
    const float* conv_w    = (const float*)d_in[7];
    const float* conv_b    = (const float*)d_in[8];
    const float* xproj_w   = (const float*)d_in[9];
    const float* dtproj_w  = (const float*)d_in[10];
    const float* dtproj_b  = (const float*)d_in[11];
    const float* A_log     = (const float*)d_in[12];
    const float* D_p       = (const float*)d_in[13];
    const float* outproj_w = (const float*)d_in[14];
    const float* normf_w   = (const float*)d_in[15];
    const float* headb_w   = (const float*)d_in[16];
    const float* headb_b   = (const float*)d_in[17];
    const float* head_w    = (const float*)d_in[18];
    const float* head_b    = (const float*)d_in[19];

    cudaFuncSetAttribute(k_mamba, cudaFuncAttributeMaxDynamicSharedMemorySize,
                         SMEM_FLOATS * sizeof(float));

    k_transpose<<<(TR_TOTAL + 255)/256, 256>>>(proj_w, inproj_w, outproj_w,
                                               xproj_w, A_log, dtproj_w, conv_w);
    k_proj<<<(B_*K_)/16, 256>>>(x, proj_b);
    k_reduce<<<1, 256>>>();
    k_mamba<<<NSEQ, 256, SMEM_FLOATS * sizeof(float)>>>(
        emb_w, emb_b, norm_w, conv_b, dtproj_b, D_p, normf_w, headb_w, headb_b);
    k_head<<<1, 256>>>(head_w, head_b, (float*)d_out);
}